// round 14
// baseline (speedup 1.0000x reference)
#include <cuda_runtime.h>
#include <cuda_fp16.h>
#include <cstdint>
#include <math.h>

#define BATCH 16
#define SEQ   1024
#define CDIM  768
#define NHEAD 12
#define HDIM  64
#define C3    (3*CDIM)
#define MTOT  (BATCH*SEQ)

// Scratch (allocation-free rule: __device__ globals)
__device__ __half g_xh[(size_t)MTOT * CDIM];
__device__ __half g_yh[(size_t)MTOT * CDIM];
__device__ __half g_qkvh[(size_t)MTOT * C3];
__device__ __half g_wat[(size_t)C3 * CDIM];
__device__ __half g_wpt[(size_t)CDIM * CDIM];

// ============================================================================
// Baseline-PTX helpers
// ============================================================================
__device__ __forceinline__ uint32_t smem_u32(const void* p) {
    uint32_t a;
    asm("{ .reg .u64 t; cvta.to.shared.u64 t, %1; cvt.u32.u64 %0, t; }"
        : "=r"(a) : "l"(p));
    return a;
}
__device__ __forceinline__ void cp_async16(uint32_t dst, const void* src) {
    asm volatile("cp.async.cg.shared.global [%0], [%1], 16;"
                 :: "r"(dst), "l"(src));
}
#define CP_COMMIT() asm volatile("cp.async.commit_group;" ::: "memory")
#define CP_WAIT(n)  asm volatile("cp.async.wait_group %0;" :: "n"(n) : "memory")

__device__ __forceinline__ void mma_f16(float* d, const uint32_t* a,
                                        const uint32_t* b) {
    asm volatile(
        "mma.sync.aligned.m16n8k16.row.col.f32.f16.f16.f32 "
        "{%0,%1,%2,%3}, {%4,%5,%6,%7}, {%8,%9}, {%0,%1,%2,%3};"
        : "+f"(d[0]), "+f"(d[1]), "+f"(d[2]), "+f"(d[3])
        : "r"(a[0]), "r"(a[1]), "r"(a[2]), "r"(a[3]),
          "r"(b[0]), "r"(b[1]));
}
__device__ __forceinline__ void ldmatrix_x4(uint32_t* r, uint32_t addr) {
    asm volatile("ldmatrix.sync.aligned.m8n8.x4.shared.b16 {%0,%1,%2,%3}, [%4];"
        : "=r"(r[0]), "=r"(r[1]), "=r"(r[2]), "=r"(r[3]) : "r"(addr));
}
__device__ __forceinline__ void ldmatrix_x4_trans(uint32_t* r, uint32_t addr) {
    asm volatile("ldmatrix.sync.aligned.m8n8.x4.trans.shared.b16 {%0,%1,%2,%3}, [%4];"
        : "=r"(r[0]), "=r"(r[1]), "=r"(r[2]), "=r"(r[3]) : "r"(addr));
}
__device__ __forceinline__ uint32_t ex2_f16x2(uint32_t x) {
    uint32_t r;
    asm("ex2.approx.f16x2 %0, %1;" : "=r"(r) : "r"(x));
    return r;
}

// ============================================================================
// Merged prep kernel (unchanged)
// ============================================================================
#define NBX ((MTOT * CDIM) / 1024)
#define NBA ((C3 / 32) * (CDIM / 32))
#define NBP ((CDIM / 32) * (CDIM / 32))

__global__ __launch_bounds__(256)
void prep_kernel(const float* __restrict__ x, __half* __restrict__ xh,
                 const float* __restrict__ Wa, __half* __restrict__ wat,
                 const float* __restrict__ Wp, __half* __restrict__ wpt)
{
    __shared__ __half t[32][33];
    const int bid = blockIdx.x;
    const int tid = threadIdx.x;

    if (bid < NBX) {
        int i = (bid * 256 + tid) * 4;
        float4 v = *(const float4*)(x + i);
        __half2 h0 = __floats2half2_rn(v.x, v.y);
        __half2 h1 = __floats2half2_rn(v.z, v.w);
        uint2 u = make_uint2(*(uint32_t*)&h0, *(uint32_t*)&h1);
        *(uint2*)(xh + i) = u;
        return;
    }

    const float* in;
    __half* out;
    int bx, by, R, Ccols;
    if (bid < NBX + NBA) {
        int tt = bid - NBX;
        bx = tt % (C3 / 32); by = tt / (C3 / 32);
        in = Wa; out = wat; R = CDIM; Ccols = C3;
    } else {
        int tt = bid - NBX - NBA;
        bx = tt % (CDIM / 32); by = tt / (CDIM / 32);
        in = Wp; out = wpt; R = CDIM; Ccols = CDIM;
    }
    const int tx = tid & 31;
    const int ty = tid >> 5;
    const int c = bx * 32 + tx;
    const int r = by * 32 + ty;
    #pragma unroll
    for (int j = 0; j < 32; j += 8)
        t[ty + j][tx] = __float2half(in[(size_t)(r + j) * Ccols + c]);
    __syncthreads();
    const int orow = bx * 32 + ty;
    const int oc   = by * 32 + tx;
    #pragma unroll
    for (int j = 0; j < 32; j += 8)
        out[(size_t)(orow + j) * R + oc] = t[tx][ty + j];
}

// ============================================================================
// fp16 mma GEMM: 256 thr, warp tile 64x32, 2 CTA/SM, BK=64, 3-stage cp.async
// with prefetch spread. Uniform epilogue (no V transpose branch anymore).
// OUT_MODE 0: fp32 out; OUT_MODE 1: half out.
// ============================================================================
#define GST 72
#define NST 3
#define STAGE_H (2 * 128 * GST)
#define GEMM_SMEM (NST * STAGE_H * 2)           // 110592 B

template<int OUT_MODE>
__global__ __launch_bounds__(256, 2)
void gemm_h_kernel(const __half* __restrict__ A, const __half* __restrict__ Bt,
                   const float* __restrict__ bias, float* __restrict__ Cf,
                   __half* __restrict__ Ch, int K, int N)
{
    extern __shared__ __half smh[];

    const int tid  = threadIdx.x;
    const int wid  = tid >> 5;
    const int lane = tid & 31;
    const int lr = lane >> 2;
    const int lq = lane & 3;
    const int bm = blockIdx.y * 128;
    const int bn = blockIdx.x * 128;
    const int warp_m = (wid & 1) * 64;
    const int warp_n = (wid >> 1) * 32;

    const int l7 = lane & 7;
    const int gA_row = (lane >> 3) & 1;
    const int gA_k   = lane >> 4;
    uint32_t aoff[4];
    #pragma unroll
    for (int mi = 0; mi < 4; mi++)
        aoff[mi] = (uint32_t)((warp_m + mi * 16 + l7 + gA_row * 8) * GST
                              + gA_k * 8);
    const int gB_k = (lane >> 3) & 1;
    const int gB_n = lane >> 4;
    uint32_t boff[2];
    #pragma unroll
    for (int nj = 0; nj < 2; nj++)
        boff[nj] = (uint32_t)((warp_n + nj * 16 + l7 + gB_n * 8) * GST
                              + gB_k * 8);

    const uint32_t smb = smem_u32(smh);

    auto load_chunk = [&](int st, int it, int i) {
        const int koff = it * 64;
        const uint32_t asb = smb + (uint32_t)(st * STAGE_H) * 2;
        const uint32_t bsb = asb + (uint32_t)(128 * GST) * 2;
        int chunk = tid + 256 * i;
        int r = chunk >> 3, c8 = chunk & 7;
        cp_async16(asb + (uint32_t)(r * GST + c8 * 8) * 2,
                   A + (size_t)(bm + r) * K + koff + c8 * 8);
        cp_async16(bsb + (uint32_t)(r * GST + c8 * 8) * 2,
                   Bt + (size_t)(bn + r) * K + koff + c8 * 8);
    };
    auto load_tile = [&](int st, int it) {
        #pragma unroll
        for (int i = 0; i < 4; ++i) load_chunk(st, it, i);
    };

    float acc[4][4][4];
    #pragma unroll
    for (int mi = 0; mi < 4; mi++)
        #pragma unroll
        for (int ni = 0; ni < 4; ni++)
            #pragma unroll
            for (int q = 0; q < 4; q++) acc[mi][ni][q] = 0.0f;

    const int nk = K / 64;
    load_tile(0, 0);
    CP_COMMIT();
    load_tile(1, 1);
    CP_COMMIT();

    for (int it = 0; it < nk; ++it) {
        CP_WAIT(1);
        __syncthreads();

        const bool pf = (it + 2 < nk);
        const int pst = (it + 2) % NST;

        const int st = it % NST;
        const uint32_t asb = smb + (uint32_t)(st * STAGE_H) * 2;
        const uint32_t bsb = asb + (uint32_t)(128 * GST) * 2;

        #pragma unroll
        for (int ks = 0; ks < 4; ks++) {
            if (pf) load_chunk(pst, it + 2, ks);

            const int k0 = ks * 16;
            uint32_t af[4][4];
            #pragma unroll
            for (int mi = 0; mi < 4; mi++)
                ldmatrix_x4(af[mi], asb + (aoff[mi] + k0) * 2);
            uint32_t bf[2][4];
            #pragma unroll
            for (int nj = 0; nj < 2; nj++)
                ldmatrix_x4(bf[nj], bsb + (boff[nj] + k0) * 2);
            #pragma unroll
            for (int mi = 0; mi < 4; mi++)
                #pragma unroll
                for (int ni = 0; ni < 4; ni++)
                    mma_f16(acc[mi][ni], af[mi], &bf[ni >> 1][(ni & 1) * 2]);
        }
        CP_COMMIT();
    }

    const int lc2 = lq * 2;
    #pragma unroll
    for (int ni = 0; ni < 4; ni++) {
        const int col = bn + warp_n + ni * 8 + lc2;
        const float2 bv = *(const float2*)(bias + col);
        #pragma unroll
        for (int mi = 0; mi < 4; mi++) {
            const int row0 = bm + warp_m + mi * 16 + lr;
            float v00 = acc[mi][ni][0] + bv.x, v01 = acc[mi][ni][1] + bv.y;
            float v10 = acc[mi][ni][2] + bv.x, v11 = acc[mi][ni][3] + bv.y;
            if (OUT_MODE == 0) {
                *(float2*)(Cf + (size_t)row0 * N + col) = make_float2(v00, v01);
                *(float2*)(Cf + (size_t)(row0 + 8) * N + col) = make_float2(v10, v11);
            } else {
                __half2 h0 = __floats2half2_rn(v00, v01);
                __half2 h1 = __floats2half2_rn(v10, v11);
                *(uint32_t*)(Ch + (size_t)row0 * N + col) = *(uint32_t*)&h0;
                *(uint32_t*)(Ch + (size_t)(row0 + 8) * N + col) = *(uint32_t*)&h1;
            }
        }
    }
}

// ============================================================================
// Flash attention: fp16 mma, register-resident P, ex2.approx.f16x2 softmax,
// masked-tile skip, 3-stage K/V pipeline w/ prefetch spread, reversed qt,
// Q prologue overlapped into stage-2 slots.
// V read row-major [t][d] from qkvh; P·V B-frags via ldmatrix.x4.trans.
// ============================================================================
#define ATC 72
#define AKV_H (64 * ATC)
#define ATTN_SMEM (6 * AKV_H * 2)    // 55296 B

__global__ __launch_bounds__(256, 2)
void attn_mma_kernel(const __half* __restrict__ qkv, __half* __restrict__ y)
{
    extern __shared__ __half smh[];

    const int tid  = threadIdx.x;
    const int wid  = tid >> 5;
    const int lane = tid & 31;
    const int lr = lane >> 2;
    const int lq = lane & 3;
    const int qt = gridDim.x - 1 - blockIdx.x;
    const int bh = blockIdx.y;
    const int b = bh / NHEAD;
    const int h = bh % NHEAD;
    const int row_base = qt * 128;

    const __half* qbase = qkv + ((size_t)(b * SEQ) + row_base) * C3 + h * HDIM;
    const __half* kbase = qkv + (size_t)(b * SEQ) * C3 + CDIM + h * HDIM;
    const __half* vbase = qkv + (size_t)(b * SEQ) * C3 + 2 * CDIM + h * HDIM;

    const int l7 = lane & 7;
    // K (non-trans) b-frag offsets: matrix rows = key index n, cols = d
    uint32_t b_off[4];
    #pragma unroll
    for (int np = 0; np < 4; np++)
        b_off[np] = (uint32_t)((np * 16 + l7 + (lane >> 4) * 8) * ATC
                               + ((lane >> 3) & 1) * 8);
    // V (trans) b-frag offsets: matrix rows = t, cols = d
    // m = lane>>3: m0 (t,d), m1 (t+8,d), m2 (t,d+8), m3 (t+8,d+8)
    uint32_t vt_off[4];
    #pragma unroll
    for (int np = 0; np < 4; np++)
        vt_off[np] = (uint32_t)((((lane >> 3) & 1) * 8 + l7) * ATC
                                + np * 16 + (lane >> 4) * 8);

    const uint32_t smb = smem_u32(smh);

    auto load_kv_chunk = [&](int st, int kt, int j) {
        const uint32_t kss = smb + (uint32_t)(st * AKV_H) * 2;
        const uint32_t vss = smb + (uint32_t)((3 + st) * AKV_H) * 2;
        int i = j & 1;
        int chunk = tid + 256 * i;
        int r = chunk >> 3, c8 = chunk & 7;
        if (j < 2) {
            cp_async16(kss + (uint32_t)(r * ATC + c8 * 8) * 2,
                       kbase + (size_t)(kt * 64 + r) * C3 + c8 * 8);
        } else {
            cp_async16(vss + (uint32_t)(r * ATC + c8 * 8) * 2,
                       vbase + (size_t)(kt * 64 + r) * C3 + c8 * 8);
        }
    };
    auto load_kv = [&](int st, int kt) {
        #pragma unroll
        for (int j = 0; j < 4; j++) load_kv_chunk(st, kt, j);
    };

    // ---- Prologue: Q into stage-2 slots, overlapped with kv0/kv1 ----
    {
        #pragma unroll
        for (int i = 0; i < 4; i++) {
            int chunk = tid + 256 * i;
            int r = chunk >> 3, c8 = chunk & 7;
            uint32_t dst = (r < 64)
                ? (uint32_t)(2 * AKV_H + r * ATC)
                : (uint32_t)(5 * AKV_H + (r - 64) * ATC);
            cp_async16(smb + (dst + c8 * 8) * 2,
                       qbase + (size_t)r * C3 + c8 * 8);
        }
        CP_COMMIT();          // group: Q
        load_kv(0, 0);
        CP_COMMIT();          // group: kv0
        load_kv(1, 1);
        CP_COMMIT();          // group: kv1
        CP_WAIT(2);           // Q done; kv0/kv1 in flight
    }
    __syncthreads();

    uint32_t aq[4][4];
    {
        const int qrow = wid * 16 + l7 + ((lane >> 3) & 1) * 8;
        const uint32_t qa_off = (wid < 4)
            ? (uint32_t)(2 * AKV_H + qrow * ATC + (lane >> 4) * 8)
            : (uint32_t)(5 * AKV_H + (qrow - 64) * ATC + (lane >> 4) * 8);
        const __half2 sc = __half2half2(__float2half(0.125f));
        #pragma unroll
        for (int kd = 0; kd < 4; kd++) {
            ldmatrix_x4(aq[kd], smb + (qa_off + kd * 16) * 2);
            #pragma unroll
            for (int q = 0; q < 4; q++) {
                __half2 t = *(__half2*)&aq[kd][q];
                t = __hmul2(t, sc);
                aq[kd][q] = *(uint32_t*)&t;
            }
        }
    }
    // Stage-2 slots first overwritten by kt=2 prefetch, ordered after the
    // kt=0 loop barrier — Q reads complete before that. No race.

    float m0 = -1e30f, m1 = -1e30f, l0 = 0.0f, l1 = 0.0f;
    float o[8][4];
    #pragma unroll
    for (int nt = 0; nt < 8; nt++)
        #pragma unroll
        for (int q = 0; q < 4; q++) o[nt][q] = 0.0f;

    const int nkt = 2 * qt + 2;
    const int warp_min_row = row_base + wid * 16;
    const int r0 = warp_min_row + lr;
    const int r1 = r0 + 8;
    const float L2E = 1.44269504f;

    for (int kt = 0; kt < nkt; kt++) {
        CP_WAIT(1);
        __syncthreads();

        const bool pf = (kt + 2 < nkt);
        const int pst = (kt + 2) % 3;

        if (kt * 64 > warp_min_row + 15) {
            if (pf) load_kv(pst, kt + 2);
            CP_COMMIT();
            continue;
        }

        const int st = kt % 3;
        const uint32_t kss = smb + (uint32_t)(st * AKV_H) * 2;
        const uint32_t vss = smb + (uint32_t)((3 + st) * AKV_H) * 2;

        float s[8][4];
        #pragma unroll
        for (int nt = 0; nt < 8; nt++)
            #pragma unroll
            for (int q = 0; q < 4; q++) s[nt][q] = 0.0f;

        #pragma unroll
        for (int kd = 0; kd < 4; kd++) {
            if (pf) load_kv_chunk(pst, kt + 2, kd);
            #pragma unroll
            for (int np = 0; np < 4; np++) {
                uint32_t bk[4];
                ldmatrix_x4(bk, kss + (b_off[np] + kd * 16) * 2);
                mma_f16(s[2 * np],     aq[kd], &bk[0]);
                mma_f16(s[2 * np + 1], aq[kd], &bk[2]);
            }
        }
        CP_COMMIT();

        if (kt * 64 + 63 > warp_min_row) {
            #pragma unroll
            for (int nt = 0; nt < 8; nt++) {
                const int c0 = kt * 64 + nt * 8 + 2 * lq;
                if (c0 > r0)     s[nt][0] = -1e30f;
                if (c0 + 1 > r0) s[nt][1] = -1e30f;
                if (c0 > r1)     s[nt][2] = -1e30f;
                if (c0 + 1 > r1) s[nt][3] = -1e30f;
            }
        }

        float mx0 = -1e30f, mx1 = -1e30f;
        #pragma unroll
        for (int nt = 0; nt < 8; nt++) {
            mx0 = fmaxf(mx0, fmaxf(s[nt][0], s[nt][1]));
            mx1 = fmaxf(mx1, fmaxf(s[nt][2], s[nt][3]));
        }
        mx0 = fmaxf(mx0, __shfl_xor_sync(0xffffffffu, mx0, 1));
        mx0 = fmaxf(mx0, __shfl_xor_sync(0xffffffffu, mx0, 2));
        mx1 = fmaxf(mx1, __shfl_xor_sync(0xffffffffu, mx1, 1));
        mx1 = fmaxf(mx1, __shfl_xor_sync(0xffffffffu, mx1, 2));

        const float mn0 = fmaxf(m0, mx0);
        const float mn1 = fmaxf(m1, mx1);
        const float a0 = __expf(m0 - mn0);
        const float a1 = __expf(m1 - mn1);
        m0 = mn0; m1 = mn1;

        uint32_t ph[8][2];
        float sum0 = 0.0f, sum1 = 0.0f;
        #pragma unroll
        for (int nt = 0; nt < 8; nt++) {
            __half2 t0 = __floats2half2_rn((s[nt][0] - mn0) * L2E,
                                           (s[nt][1] - mn0) * L2E);
            __half2 t1 = __floats2half2_rn((s[nt][2] - mn1) * L2E,
                                           (s[nt][3] - mn1) * L2E);
            ph[nt][0] = ex2_f16x2(*(uint32_t*)&t0);
            ph[nt][1] = ex2_f16x2(*(uint32_t*)&t1);
            float2 f0 = __half22float2(*(__half2*)&ph[nt][0]);
            float2 f1 = __half22float2(*(__half2*)&ph[nt][1]);
            sum0 += f0.x + f0.y;
            sum1 += f1.x + f1.y;
        }
        sum0 += __shfl_xor_sync(0xffffffffu, sum0, 1);
        sum0 += __shfl_xor_sync(0xffffffffu, sum0, 2);
        sum1 += __shfl_xor_sync(0xffffffffu, sum1, 1);
        sum1 += __shfl_xor_sync(0xffffffffu, sum1, 2);
        l0 = l0 * a0 + sum0;
        l1 = l1 * a1 + sum1;

        #pragma unroll
        for (int nt = 0; nt < 8; nt++) {
            o[nt][0] *= a0; o[nt][1] *= a0;
            o[nt][2] *= a1; o[nt][3] *= a1;
        }

        // ---- O += P @ V : V [t][d] via ldmatrix.trans ----
        #pragma unroll
        for (int kj = 0; kj < 4; kj++) {
            uint32_t ap[4] = { ph[2*kj][0], ph[2*kj][1],
                               ph[2*kj+1][0], ph[2*kj+1][1] };
            #pragma unroll
            for (int np = 0; np < 4; np++) {
                uint32_t bv[4];
                ldmatrix_x4_trans(bv, vss + (vt_off[np] + kj * 16 * ATC) * 2);
                mma_f16(o[2 * np],     ap, &bv[0]);
                mma_f16(o[2 * np + 1], ap, &bv[2]);
            }
        }
    }

    const float inv0 = 1.0f / l0;
    const float inv1 = 1.0f / l1;
    __half* y0 = y + (size_t)(b * SEQ + r0) * CDIM + h * HDIM;
    __half* y1 = y + (size_t)(b * SEQ + r1) * CDIM + h * HDIM;
    #pragma unroll
    for (int nt = 0; nt < 8; nt++) {
        const int c = nt * 8 + 2 * lq;
        __half2 h0 = __floats2half2_rn(o[nt][0] * inv0, o[nt][1] * inv0);
        __half2 h1 = __floats2half2_rn(o[nt][2] * inv1, o[nt][3] * inv1);
        *(uint32_t*)(y0 + c) = *(uint32_t*)&h0;
        *(uint32_t*)(y1 + c) = *(uint32_t*)&h1;
    }
}

// ---------------------------------------------------------------------------
extern "C" void kernel_launch(void* const* d_in, const int* in_sizes, int n_in,
                              void* d_out, int out_size)
{
    const float* x      = (const float*)d_in[0];
    const float* W_attn = (const float*)d_in[1];
    const float* b_attn = (const float*)d_in[2];
    const float* W_proj = (const float*)d_in[3];
    const float* b_proj = (const float*)d_in[4];
    float* out = (float*)d_out;

    __half *xh, *yh, *qkvh, *wat, *wpt;
    cudaGetSymbolAddress((void**)&xh, g_xh);
    cudaGetSymbolAddress((void**)&yh, g_yh);
    cudaGetSymbolAddress((void**)&qkvh, g_qkvh);
    cudaGetSymbolAddress((void**)&wat, g_wat);
    cudaGetSymbolAddress((void**)&wpt, g_wpt);

    // 0) merged prep
    prep_kernel<<<NBX + NBA + NBP, 256>>>(x, xh, W_attn, wat, W_proj, wpt);

    // 1) QKV projection (uniform half epilogue; V stays row-major in qkvh)
    {
        cudaFuncSetAttribute(gemm_h_kernel<1>,
                             cudaFuncAttributeMaxDynamicSharedMemorySize,
                             GEMM_SMEM);
        dim3 grid(C3 / 128, MTOT / 128);
        gemm_h_kernel<1><<<grid, 256, GEMM_SMEM>>>(xh, wat, b_attn, nullptr,
                                                   qkvh, CDIM, C3);
    }
    // 2) Flash attention (V via ldmatrix.trans)
    {
        cudaFuncSetAttribute(attn_mma_kernel,
                             cudaFuncAttributeMaxDynamicSharedMemorySize,
                             ATTN_SMEM);
        dim3 grid(SEQ / 128, BATCH * NHEAD);
        attn_mma_kernel<<<grid, 256, ATTN_SMEM>>>(qkvh, yh);
    }
    // 3) Output projection
    {
        cudaFuncSetAttribute(gemm_h_kernel<0>,
                             cudaFuncAttributeMaxDynamicSharedMemorySize,
                             GEMM_SMEM);
        dim3 grid(CDIM / 128, MTOT / 128);
        gemm_h_kernel<0><<<grid, 256, GEMM_SMEM>>>(yh, wpt, b_proj, out,
                                                   nullptr, CDIM, CDIM);
    }
}

// round 15
// speedup vs baseline: 1.0236x; 1.0236x over previous
#include <cuda_runtime.h>
#include <cuda_fp16.h>
#include <cstdint>
#include <math.h>

#define BATCH 16
#define SEQ   1024
#define CDIM  768
#define NHEAD 12
#define HDIM  64
#define C3    (3*CDIM)
#define MTOT  (BATCH*SEQ)

// Scratch (allocation-free rule: __device__ globals)
__device__ __half g_xh[(size_t)MTOT * CDIM];
__device__ __half g_yh[(size_t)MTOT * CDIM];
__device__ __half g_qkvh[(size_t)MTOT * C3];
__device__ __half g_vt[(size_t)BATCH * NHEAD * HDIM * SEQ]; // v [b,h,d,t]
__device__ __half g_wat[(size_t)C3 * CDIM];
__device__ __half g_wpt[(size_t)CDIM * CDIM];

// ============================================================================
// Baseline-PTX helpers
// ============================================================================
__device__ __forceinline__ uint32_t smem_u32(const void* p) {
    uint32_t a;
    asm("{ .reg .u64 t; cvta.to.shared.u64 t, %1; cvt.u32.u64 %0, t; }"
        : "=r"(a) : "l"(p));
    return a;
}
__device__ __forceinline__ void cp_async16(uint32_t dst, const void* src) {
    asm volatile("cp.async.cg.shared.global [%0], [%1], 16;"
                 :: "r"(dst), "l"(src));
}
#define CP_COMMIT() asm volatile("cp.async.commit_group;" ::: "memory")
#define CP_WAIT(n)  asm volatile("cp.async.wait_group %0;" :: "n"(n) : "memory")

__device__ __forceinline__ void mma_f16(float* d, const uint32_t* a,
                                        const uint32_t* b) {
    asm volatile(
        "mma.sync.aligned.m16n8k16.row.col.f32.f16.f16.f32 "
        "{%0,%1,%2,%3}, {%4,%5,%6,%7}, {%8,%9}, {%0,%1,%2,%3};"
        : "+f"(d[0]), "+f"(d[1]), "+f"(d[2]), "+f"(d[3])
        : "r"(a[0]), "r"(a[1]), "r"(a[2]), "r"(a[3]),
          "r"(b[0]), "r"(b[1]));
}
__device__ __forceinline__ void ldmatrix_x4(uint32_t* r, uint32_t addr) {
    asm volatile("ldmatrix.sync.aligned.m8n8.x4.shared.b16 {%0,%1,%2,%3}, [%4];"
        : "=r"(r[0]), "=r"(r[1]), "=r"(r[2]), "=r"(r[3]) : "r"(addr));
}
__device__ __forceinline__ uint32_t ex2_f16x2(uint32_t x) {
    uint32_t r;
    asm("ex2.approx.f16x2 %0, %1;" : "=r"(r) : "r"(x));
    return r;
}

// ============================================================================
// Merged prep kernel (unchanged)
// ============================================================================
#define NBX ((MTOT * CDIM) / 1024)
#define NBA ((C3 / 32) * (CDIM / 32))
#define NBP ((CDIM / 32) * (CDIM / 32))

__global__ __launch_bounds__(256)
void prep_kernel(const float* __restrict__ x, __half* __restrict__ xh,
                 const float* __restrict__ Wa, __half* __restrict__ wat,
                 const float* __restrict__ Wp, __half* __restrict__ wpt)
{
    __shared__ __half t[32][33];
    const int bid = blockIdx.x;
    const int tid = threadIdx.x;

    if (bid < NBX) {
        int i = (bid * 256 + tid) * 4;
        float4 v = *(const float4*)(x + i);
        __half2 h0 = __floats2half2_rn(v.x, v.y);
        __half2 h1 = __floats2half2_rn(v.z, v.w);
        uint2 u = make_uint2(*(uint32_t*)&h0, *(uint32_t*)&h1);
        *(uint2*)(xh + i) = u;
        return;
    }

    const float* in;
    __half* out;
    int bx, by, R, Ccols;
    if (bid < NBX + NBA) {
        int tt = bid - NBX;
        bx = tt % (C3 / 32); by = tt / (C3 / 32);
        in = Wa; out = wat; R = CDIM; Ccols = C3;
    } else {
        int tt = bid - NBX - NBA;
        bx = tt % (CDIM / 32); by = tt / (CDIM / 32);
        in = Wp; out = wpt; R = CDIM; Ccols = CDIM;
    }
    const int tx = tid & 31;
    const int ty = tid >> 5;
    const int c = bx * 32 + tx;
    const int r = by * 32 + ty;
    #pragma unroll
    for (int j = 0; j < 32; j += 8)
        t[ty + j][tx] = __float2half(in[(size_t)(r + j) * Ccols + c]);
    __syncthreads();
    const int orow = bx * 32 + ty;
    const int oc   = by * 32 + tx;
    #pragma unroll
    for (int j = 0; j < 32; j += 8)
        out[(size_t)(orow + j) * R + oc] = t[tx][ty + j];
}

// ============================================================================
// fp16 mma GEMM (R13 config): 256 thr, warp tile 64x32, 2 CTA/SM, BK=64,
// 3-stage cp.async with prefetch spread over k-steps. V-transpose epilogue.
// ============================================================================
#define GST 72
#define NST 3
#define STAGE_H (2 * 128 * GST)
#define GEMM_SMEM (NST * STAGE_H * 2)           // 110592 B
#define VTS 136

template<int OUT_MODE>
__global__ __launch_bounds__(256, 2)
void gemm_h_kernel(const __half* __restrict__ A, const __half* __restrict__ Bt,
                   const float* __restrict__ bias, float* __restrict__ Cf,
                   __half* __restrict__ Ch, __half* __restrict__ vt,
                   int K, int N)
{
    extern __shared__ __half smh[];

    const int tid  = threadIdx.x;
    const int wid  = tid >> 5;
    const int lane = tid & 31;
    const int lr = lane >> 2;
    const int lq = lane & 3;
    const int bm = blockIdx.y * 128;
    const int bn = blockIdx.x * 128;
    const int warp_m = (wid & 1) * 64;
    const int warp_n = (wid >> 1) * 32;

    const int l7 = lane & 7;
    const int gA_row = (lane >> 3) & 1;
    const int gA_k   = lane >> 4;
    uint32_t aoff[4];
    #pragma unroll
    for (int mi = 0; mi < 4; mi++)
        aoff[mi] = (uint32_t)((warp_m + mi * 16 + l7 + gA_row * 8) * GST
                              + gA_k * 8);
    const int gB_k = (lane >> 3) & 1;
    const int gB_n = lane >> 4;
    uint32_t boff[2];
    #pragma unroll
    for (int nj = 0; nj < 2; nj++)
        boff[nj] = (uint32_t)((warp_n + nj * 16 + l7 + gB_n * 8) * GST
                              + gB_k * 8);

    const uint32_t smb = smem_u32(smh);

    auto load_chunk = [&](int st, int it, int i) {
        const int koff = it * 64;
        const uint32_t asb = smb + (uint32_t)(st * STAGE_H) * 2;
        const uint32_t bsb = asb + (uint32_t)(128 * GST) * 2;
        int chunk = tid + 256 * i;
        int r = chunk >> 3, c8 = chunk & 7;
        cp_async16(asb + (uint32_t)(r * GST + c8 * 8) * 2,
                   A + (size_t)(bm + r) * K + koff + c8 * 8);
        cp_async16(bsb + (uint32_t)(r * GST + c8 * 8) * 2,
                   Bt + (size_t)(bn + r) * K + koff + c8 * 8);
    };
    auto load_tile = [&](int st, int it) {
        #pragma unroll
        for (int i = 0; i < 4; ++i) load_chunk(st, it, i);
    };

    float acc[4][4][4];
    #pragma unroll
    for (int mi = 0; mi < 4; mi++)
        #pragma unroll
        for (int ni = 0; ni < 4; ni++)
            #pragma unroll
            for (int q = 0; q < 4; q++) acc[mi][ni][q] = 0.0f;

    const int nk = K / 64;
    load_tile(0, 0);
    CP_COMMIT();
    load_tile(1, 1);
    CP_COMMIT();

    for (int it = 0; it < nk; ++it) {
        CP_WAIT(1);
        __syncthreads();

        const bool pf = (it + 2 < nk);
        const int pst = (it + 2) % NST;

        const int st = it % NST;
        const uint32_t asb = smb + (uint32_t)(st * STAGE_H) * 2;
        const uint32_t bsb = asb + (uint32_t)(128 * GST) * 2;

        #pragma unroll
        for (int ks = 0; ks < 4; ks++) {
            if (pf) load_chunk(pst, it + 2, ks);

            const int k0 = ks * 16;
            uint32_t af[4][4];
            #pragma unroll
            for (int mi = 0; mi < 4; mi++)
                ldmatrix_x4(af[mi], asb + (aoff[mi] + k0) * 2);
            uint32_t bf[2][4];
            #pragma unroll
            for (int nj = 0; nj < 2; nj++)
                ldmatrix_x4(bf[nj], bsb + (boff[nj] + k0) * 2);
            #pragma unroll
            for (int mi = 0; mi < 4; mi++)
                #pragma unroll
                for (int ni = 0; ni < 4; ni++)
                    mma_f16(acc[mi][ni], af[mi], &bf[ni >> 1][(ni & 1) * 2]);
        }
        CP_COMMIT();
    }

    const int lc2 = lq * 2;
    const bool is_v = (OUT_MODE == 1) && (bn >= 2 * CDIM);

    if (is_v) {
        __syncthreads();
        __half* Vt = smh;
        #pragma unroll
        for (int ni = 0; ni < 4; ni++) {
            const int c = warp_n + ni * 8 + lc2;
            const float2 bv = *(const float2*)(bias + bn + c);
            #pragma unroll
            for (int mi = 0; mi < 4; mi++) {
                const int r = warp_m + mi * 16 + lr;
                Vt[(c    ) * VTS + r    ] = __float2half(acc[mi][ni][0] + bv.x);
                Vt[(c + 1) * VTS + r    ] = __float2half(acc[mi][ni][1] + bv.y);
                Vt[(c    ) * VTS + r + 8] = __float2half(acc[mi][ni][2] + bv.x);
                Vt[(c + 1) * VTS + r + 8] = __float2half(acc[mi][ni][3] + bv.y);
            }
        }
        __syncthreads();
        const int b = bm >> 10;
        const int t0 = bm & 1023;
        for (int i = tid; i < 128 * 16; i += 256) {
            const int c  = i >> 4;
            const int x8 = (i & 15) * 8;
            const int colv = bn - 2 * CDIM + c;
            const int h = colv >> 6, d = colv & 63;
            uint4 val = *(const uint4*)&Vt[c * VTS + x8];
            *(uint4*)(vt + ((size_t)(b * NHEAD + h) * HDIM + d) * SEQ + t0 + x8) = val;
        }
        return;
    }

    #pragma unroll
    for (int ni = 0; ni < 4; ni++) {
        const int col = bn + warp_n + ni * 8 + lc2;
        const float2 bv = *(const float2*)(bias + col);
        #pragma unroll
        for (int mi = 0; mi < 4; mi++) {
            const int row0 = bm + warp_m + mi * 16 + lr;
            float v00 = acc[mi][ni][0] + bv.x, v01 = acc[mi][ni][1] + bv.y;
            float v10 = acc[mi][ni][2] + bv.x, v11 = acc[mi][ni][3] + bv.y;
            if (OUT_MODE == 0) {
                *(float2*)(Cf + (size_t)row0 * N + col) = make_float2(v00, v01);
                *(float2*)(Cf + (size_t)(row0 + 8) * N + col) = make_float2(v10, v11);
            } else {
                __half2 h0 = __floats2half2_rn(v00, v01);
                __half2 h1 = __floats2half2_rn(v10, v11);
                *(uint32_t*)(Ch + (size_t)row0 * N + col) = *(uint32_t*)&h0;
                *(uint32_t*)(Ch + (size_t)(row0 + 8) * N + col) = *(uint32_t*)&h1;
            }
        }
    }
}

// ============================================================================
// Flash attention (R13 + deferred l-sum reduction): fp16 mma, register-
// resident P, ex2.approx.f16x2 softmax, masked-tile skip, 3-stage K/V
// pipeline with prefetch spread, reversed qt, Q-prologue overlap.
// l kept as per-lane partial; cross-lane reduced once in the epilogue.
// ============================================================================
#define ATC 72
#define AKV_H (64 * ATC)
#define ATTN_SMEM (6 * AKV_H * 2)    // 55296 B

__global__ __launch_bounds__(256, 2)
void attn_mma_kernel(const __half* __restrict__ qkv,
                     const __half* __restrict__ vt,
                     __half* __restrict__ y)
{
    extern __shared__ __half smh[];

    const int tid  = threadIdx.x;
    const int wid  = tid >> 5;
    const int lane = tid & 31;
    const int lr = lane >> 2;
    const int lq = lane & 3;
    const int qt = gridDim.x - 1 - blockIdx.x;
    const int bh = blockIdx.y;
    const int b = bh / NHEAD;
    const int h = bh % NHEAD;
    const int row_base = qt * 128;

    const __half* qbase = qkv + ((size_t)(b * SEQ) + row_base) * C3 + h * HDIM;
    const __half* kbase = qkv + (size_t)(b * SEQ) * C3 + CDIM + h * HDIM;
    const __half* vbase = vt + (size_t)(b * NHEAD + h) * HDIM * SEQ;

    const int l7 = lane & 7;
    uint32_t b_off[4];
    #pragma unroll
    for (int np = 0; np < 4; np++)
        b_off[np] = (uint32_t)((np * 16 + l7 + (lane >> 4) * 8) * ATC
                               + ((lane >> 3) & 1) * 8);

    const uint32_t smb = smem_u32(smh);

    auto load_kv_chunk = [&](int st, int kt, int j) {
        const uint32_t kss = smb + (uint32_t)(st * AKV_H) * 2;
        const uint32_t vss = smb + (uint32_t)((3 + st) * AKV_H) * 2;
        int i = j & 1;
        int chunk = tid + 256 * i;
        int r = chunk >> 3, c8 = chunk & 7;
        if (j < 2) {
            cp_async16(kss + (uint32_t)(r * ATC + c8 * 8) * 2,
                       kbase + (size_t)(kt * 64 + r) * C3 + c8 * 8);
        } else {
            cp_async16(vss + (uint32_t)(r * ATC + c8 * 8) * 2,
                       vbase + (size_t)r * SEQ + kt * 64 + c8 * 8);
        }
    };
    auto load_kv = [&](int st, int kt) {
        #pragma unroll
        for (int j = 0; j < 4; j++) load_kv_chunk(st, kt, j);
    };

    // ---- Prologue: Q into stage-2 slots, overlapped with kv0/kv1 ----
    {
        #pragma unroll
        for (int i = 0; i < 4; i++) {
            int chunk = tid + 256 * i;
            int r = chunk >> 3, c8 = chunk & 7;
            uint32_t dst = (r < 64)
                ? (uint32_t)(2 * AKV_H + r * ATC)
                : (uint32_t)(5 * AKV_H + (r - 64) * ATC);
            cp_async16(smb + (dst + c8 * 8) * 2,
                       qbase + (size_t)r * C3 + c8 * 8);
        }
        CP_COMMIT();          // group: Q
        load_kv(0, 0);
        CP_COMMIT();          // group: kv0
        load_kv(1, 1);
        CP_COMMIT();          // group: kv1
        CP_WAIT(2);           // Q done; kv0/kv1 in flight
    }
    __syncthreads();

    uint32_t aq[4][4];
    {
        const int qrow = wid * 16 + l7 + ((lane >> 3) & 1) * 8;
        const uint32_t qa_off = (wid < 4)
            ? (uint32_t)(2 * AKV_H + qrow * ATC + (lane >> 4) * 8)
            : (uint32_t)(5 * AKV_H + (qrow - 64) * ATC + (lane >> 4) * 8);
        const __half2 sc = __half2half2(__float2half(0.125f));
        #pragma unroll
        for (int kd = 0; kd < 4; kd++) {
            ldmatrix_x4(aq[kd], smb + (qa_off + kd * 16) * 2);
            #pragma unroll
            for (int q = 0; q < 4; q++) {
                __half2 t = *(__half2*)&aq[kd][q];
                t = __hmul2(t, sc);
                aq[kd][q] = *(uint32_t*)&t;
            }
        }
    }
    // Stage-2 slots first overwritten by kt=2 prefetch, ordered after the
    // kt=0 loop barrier — Q reads complete before that. No race.

    float m0 = -1e30f, m1 = -1e30f, l0 = 0.0f, l1 = 0.0f;  // l: per-lane partial
    float o[8][4];
    #pragma unroll
    for (int nt = 0; nt < 8; nt++)
        #pragma unroll
        for (int q = 0; q < 4; q++) o[nt][q] = 0.0f;

    const int nkt = 2 * qt + 2;
    const int warp_min_row = row_base + wid * 16;
    const int r0 = warp_min_row + lr;
    const int r1 = r0 + 8;
    const float L2E = 1.44269504f;

    for (int kt = 0; kt < nkt; kt++) {
        CP_WAIT(1);
        __syncthreads();

        const bool pf = (kt + 2 < nkt);
        const int pst = (kt + 2) % 3;

        if (kt * 64 > warp_min_row + 15) {
            if (pf) load_kv(pst, kt + 2);
            CP_COMMIT();
            continue;
        }

        const int st = kt % 3;
        const uint32_t kss = smb + (uint32_t)(st * AKV_H) * 2;
        const uint32_t vss = smb + (uint32_t)((3 + st) * AKV_H) * 2;

        float s[8][4];
        #pragma unroll
        for (int nt = 0; nt < 8; nt++)
            #pragma unroll
            for (int q = 0; q < 4; q++) s[nt][q] = 0.0f;

        #pragma unroll
        for (int kd = 0; kd < 4; kd++) {
            if (pf) load_kv_chunk(pst, kt + 2, kd);
            #pragma unroll
            for (int np = 0; np < 4; np++) {
                uint32_t bk[4];
                ldmatrix_x4(bk, kss + (b_off[np] + kd * 16) * 2);
                mma_f16(s[2 * np],     aq[kd], &bk[0]);
                mma_f16(s[2 * np + 1], aq[kd], &bk[2]);
            }
        }
        CP_COMMIT();

        if (kt * 64 + 63 > warp_min_row) {
            #pragma unroll
            for (int nt = 0; nt < 8; nt++) {
                const int c0 = kt * 64 + nt * 8 + 2 * lq;
                if (c0 > r0)     s[nt][0] = -1e30f;
                if (c0 + 1 > r0) s[nt][1] = -1e30f;
                if (c0 > r1)     s[nt][2] = -1e30f;
                if (c0 + 1 > r1) s[nt][3] = -1e30f;
            }
        }

        // ---- online softmax: max must be reduced per-tile; sum is deferred ----
        float mx0 = -1e30f, mx1 = -1e30f;
        #pragma unroll
        for (int nt = 0; nt < 8; nt++) {
            mx0 = fmaxf(mx0, fmaxf(s[nt][0], s[nt][1]));
            mx1 = fmaxf(mx1, fmaxf(s[nt][2], s[nt][3]));
        }
        mx0 = fmaxf(mx0, __shfl_xor_sync(0xffffffffu, mx0, 1));
        mx0 = fmaxf(mx0, __shfl_xor_sync(0xffffffffu, mx0, 2));
        mx1 = fmaxf(mx1, __shfl_xor_sync(0xffffffffu, mx1, 1));
        mx1 = fmaxf(mx1, __shfl_xor_sync(0xffffffffu, mx1, 2));

        const float mn0 = fmaxf(m0, mx0);
        const float mn1 = fmaxf(m1, mx1);
        const float a0 = __expf(m0 - mn0);
        const float a1 = __expf(m1 - mn1);
        m0 = mn0; m1 = mn1;

        uint32_t ph[8][2];
        float sum0 = 0.0f, sum1 = 0.0f;   // per-lane partials (no shuffles)
        #pragma unroll
        for (int nt = 0; nt < 8; nt++) {
            __half2 t0 = __floats2half2_rn((s[nt][0] - mn0) * L2E,
                                           (s[nt][1] - mn0) * L2E);
            __half2 t1 = __floats2half2_rn((s[nt][2] - mn1) * L2E,
                                           (s[nt][3] - mn1) * L2E);
            ph[nt][0] = ex2_f16x2(*(uint32_t*)&t0);
            ph[nt][1] = ex2_f16x2(*(uint32_t*)&t1);
            float2 f0 = __half22float2(*(__half2*)&ph[nt][0]);
            float2 f1 = __half22float2(*(__half2*)&ph[nt][1]);
            sum0 += f0.x + f0.y;
            sum1 += f1.x + f1.y;
        }
        l0 = l0 * a0 + sum0;   // per-lane partial l; a uniform across quad
        l1 = l1 * a1 + sum1;

        #pragma unroll
        for (int nt = 0; nt < 8; nt++) {
            o[nt][0] *= a0; o[nt][1] *= a0;
            o[nt][2] *= a1; o[nt][3] *= a1;
        }

        #pragma unroll
        for (int kj = 0; kj < 4; kj++) {
            uint32_t ap[4] = { ph[2*kj][0], ph[2*kj][1],
                               ph[2*kj+1][0], ph[2*kj+1][1] };
            #pragma unroll
            for (int np = 0; np < 4; np++) {
                uint32_t bv[4];
                ldmatrix_x4(bv, vss + (b_off[np] + kj * 16) * 2);
                mma_f16(o[2 * np],     ap, &bv[0]);
                mma_f16(o[2 * np + 1], ap, &bv[2]);
            }
        }
    }

    // ---- epilogue: reduce l across the quad once, normalize, store ----
    l0 += __shfl_xor_sync(0xffffffffu, l0, 1);
    l0 += __shfl_xor_sync(0xffffffffu, l0, 2);
    l1 += __shfl_xor_sync(0xffffffffu, l1, 1);
    l1 += __shfl_xor_sync(0xffffffffu, l1, 2);

    const float inv0 = 1.0f / l0;
    const float inv1 = 1.0f / l1;
    __half* y0 = y + (size_t)(b * SEQ + r0) * CDIM + h * HDIM;
    __half* y1 = y + (size_t)(b * SEQ + r1) * CDIM + h * HDIM;
    #pragma unroll
    for (int nt = 0; nt < 8; nt++) {
        const int c = nt * 8 + 2 * lq;
        __half2 h0 = __floats2half2_rn(o[nt][0] * inv0, o[nt][1] * inv0);
        __half2 h1 = __floats2half2_rn(o[nt][2] * inv1, o[nt][3] * inv1);
        *(uint32_t*)(y0 + c) = *(uint32_t*)&h0;
        *(uint32_t*)(y1 + c) = *(uint32_t*)&h1;
    }
}

// ---------------------------------------------------------------------------
extern "C" void kernel_launch(void* const* d_in, const int* in_sizes, int n_in,
                              void* d_out, int out_size)
{
    const float* x      = (const float*)d_in[0];
    const float* W_attn = (const float*)d_in[1];
    const float* b_attn = (const float*)d_in[2];
    const float* W_proj = (const float*)d_in[3];
    const float* b_proj = (const float*)d_in[4];
    float* out = (float*)d_out;

    __half *xh, *yh, *qkvh, *vt, *wat, *wpt;
    cudaGetSymbolAddress((void**)&xh, g_xh);
    cudaGetSymbolAddress((void**)&yh, g_yh);
    cudaGetSymbolAddress((void**)&qkvh, g_qkvh);
    cudaGetSymbolAddress((void**)&vt, g_vt);
    cudaGetSymbolAddress((void**)&wat, g_wat);
    cudaGetSymbolAddress((void**)&wpt, g_wpt);

    // 0) merged prep
    prep_kernel<<<NBX + NBA + NBP, 256>>>(x, xh, W_attn, wat, W_proj, wpt);

    // 1) QKV projection (R13 config: V transposed in epilogue)
    {
        cudaFuncSetAttribute(gemm_h_kernel<1>,
                             cudaFuncAttributeMaxDynamicSharedMemorySize,
                             GEMM_SMEM);
        dim3 grid(C3 / 128, MTOT / 128);
        gemm_h_kernel<1><<<grid, 256, GEMM_SMEM>>>(xh, wat, b_attn, nullptr,
                                                   qkvh, vt, CDIM, C3);
    }
    // 2) Flash attention
    {
        cudaFuncSetAttribute(attn_mma_kernel,
                             cudaFuncAttributeMaxDynamicSharedMemorySize,
                             ATTN_SMEM);
        dim3 grid(SEQ / 128, BATCH * NHEAD);
        attn_mma_kernel<<<grid, 256, ATTN_SMEM>>>(qkvh, vt, yh);
    }
    // 3) Output projection
    {
        cudaFuncSetAttribute(gemm_h_kernel<0>,
                             cudaFuncAttributeMaxDynamicSharedMemorySize,
                             GEMM_SMEM);
        dim3 grid(CDIM / 128, MTOT / 128);
        gemm_h_kernel<0><<<grid, 256, GEMM_SMEM>>>(yh, wpt, b_proj, out,
                                                   nullptr, nullptr,
                                                   CDIM, CDIM);
    }
}